// round 9
// baseline (speedup 1.0000x reference)
#include <cuda_runtime.h>
#include <cuda_fp16.h>

// ---- problem constants ----
#define Bb   32      // batch
#define Ii   32      // input capsules
#define AIN  16      // input atoms
#define OD   10      // output classes
#define OA   16      // output atoms
#define HWp  144     // 12*12 spatial
#define Kk   160     // OD*OA
#define Sp   8       // positions per block
#define NCH  (HWp/Sp)   // 18 chunks
#define VPAD 34      // capsule-dim stride in half2 (keeps LDS.64 reads 8B-aligned)

// staging: w[i] (2560 floats) + x[i] tile (16 ain x 8 pos = 128 floats)
#define WST   (AIN * Kk)          // 2560
#define XST   (AIN * Sp)          // 128
#define STG   (WST + XST)         // 2688 floats = 10752 B per buffer

// dynamic smem layout (bytes)
#define VSM_BYTES  (4 * Kk * VPAD * 4)             // 87040 (half2 votes)
#define STG_OFF    VSM_BYTES                       // 87040
#define EX_OFF     (STG_OFF + 2 * STG * 4)         // +21504 = 108544
#define SMEM_BYTES (EX_OFF + 2 * OD * 16 * 16)     // +5120  = 113664

// ============================================================================
// Fused kernel v2: block = (b, 8-position chunk). 320 threads = 10 warps.
// Phase 1: per-capsule double-buffered smem staging of (w[i], x[i]) with
//          register prefetch one capsule ahead; ONE __syncthreads per capsule.
//          Votes -> smem fp16 half2(pos_even, pos_odd).
// Phase 2: routing per position pair (identical to R8's proven phase 2).
// ============================================================================
__global__ void __launch_bounds__(320, 2)
fused_kernel(const float* __restrict__ x, const float* __restrict__ w,
             const float* __restrict__ bias, float* __restrict__ out)
{
    extern __shared__ char smem_raw[];
    __half2* vsm   = (__half2*)smem_raw;                  // votes
    float*   stage = (float*)(smem_raw + STG_OFF);        // 2 x STG floats
    float4*  ex    = (float4*)(smem_raw + EX_OFF);        // softmax exchange

    const int b   = blockIdx.x / NCH;
    const int hw0 = (blockIdx.x % NCH) * Sp;
    const int tid = threadIdx.x;

    // ---- cooperative loader for capsule i -> 9 regs ----
    auto coop_load = [&](int i, float* wp) {
#pragma unroll
        for (int k = 0; k < 9; k++) {
            const int idx = tid + k * 320;
            if (idx < STG) {
                if (idx < WST) {
                    wp[k] = w[i * WST + idx];                      // coalesced
                } else {
                    const int j   = idx - WST;                     // 0..127
                    const int ain = j >> 3;
                    const int p   = j & 7;
                    wp[k] = x[((size_t)(b * Ii + i) * AIN + ain) * HWp + hw0 + p];
                }
            }
        }
    };
    auto coop_store = [&](int buf, const float* wp) {
        float* dst = stage + buf * STG;
#pragma unroll
        for (int k = 0; k < 9; k++) {
            const int idx = tid + k * 320;
            if (idx < STG) dst[idx] = wp[k];
        }
    };

    // ================= Phase 1: votes =================
    {
        const int t = tid % Kk;          // weight column = d*16+a
        const int h = tid / Kk;          // 0/1 -> positions 4h..4h+3

        float wp[9];
        coop_load(0, wp);
        coop_store(0, wp);
        coop_load(1, wp);
        __syncthreads();                 // buf0 ready

        for (int i = 0; i < Ii; i++) {
            // publish i+1 into the non-read buffer; start fetching i+2
            if (i + 1 < Ii) {
                coop_store((i + 1) & 1, wp);
                if (i + 2 < Ii) coop_load(i + 2, wp);
            }

            const float* wb = stage + (i & 1) * STG;
            const float* xb = wb + WST;

            float a0 = 0.f, a1 = 0.f, a2 = 0.f, a3 = 0.f;
#pragma unroll
            for (int ain = 0; ain < AIN; ain++) {
                const float  wv = wb[ain * Kk + t];                // LDS conflict-free
                const float4 xv = *(const float4*)&xb[ain * Sp + 4 * h]; // broadcast
                a0 = fmaf(wv, xv.x, a0);
                a1 = fmaf(wv, xv.y, a1);
                a2 = fmaf(wv, xv.z, a2);
                a3 = fmaf(wv, xv.w, a3);
            }
            vsm[((2 * h)     * Kk + t) * VPAD + i] = __floats2half2_rn(a0, a1);
            vsm[((2 * h + 1) * Kk + t) * VPAD + i] = __floats2half2_rn(a2, a3);

            __syncthreads();             // i+1 buffer ready; i's reads done
        }
    }

    // ================= Phase 2: routing (R8's proven version) =================
    const int d    = tid >> 5;             // warp = class
    const int lane = tid & 31;
    const int i16  = lane & 15;            // capsule pair (capsules 2*i16, 2*i16+1)
    const int grp  = lane >> 4;            // atom half
    const int atom = grp * 8 + ((lane >> 1) & 7);
    const float bv = bias[d * OA + atom];
    const unsigned FULL = 0xffffffffu;

    for (int q = 0; q < Sp / 2; q++) {
        float va0p0[8], va0p1[8], va1p0[8], va1p1[8];
#pragma unroll
        for (int k = 0; k < 8; k++) {
            const int row = (q * Kk + d * OA + grp * 8 + k) * VPAD + 2 * i16;
            const uint2 u = *(const uint2*)&vsm[row];    // LDS.64, 8B-aligned
            const float2 f0 = __half22float2(*(const __half2*)&u.x);
            const float2 f1 = __half22float2(*(const __half2*)&u.y);
            va0p0[k] = f0.x; va0p1[k] = f0.y;
            va1p0[k] = f1.x; va1p1[k] = f1.y;
        }

        float lA0 = 0.f, lB0 = 0.f, lA1 = 0.f, lB1 = 0.f;
        float P0 = 0.f, P1 = 0.f, sc0 = 0.f, sc1 = 0.f;

#pragma unroll
        for (int r = 0; r < 3; r++) {
            float rA0, rB0, rA1, rB1;
            if (r == 0) {
                rA0 = rB0 = rA1 = rB1 = 0.1f;
            } else {
                const float eA0 = __expf(lA0), eB0 = __expf(lB0);
                const float eA1 = __expf(lA1), eB1 = __expf(lB1);
                if (grp == 0)
                    ex[(r - 1) * OD * 16 + d * 16 + i16] = make_float4(eA0, eB0, eA1, eB1);
                __syncthreads();
                float sA0 = 0.f, sB0 = 0.f, sA1 = 0.f, sB1 = 0.f;
#pragma unroll
                for (int d2 = 0; d2 < OD; d2++) {
                    const float4 v = ex[(r - 1) * OD * 16 + d2 * 16 + i16];
                    sA0 += v.x; sB0 += v.y; sA1 += v.z; sB1 += v.w;
                }
                rA0 = __fdividef(eA0, sA0); rB0 = __fdividef(eB0, sB0);
                rA1 = __fdividef(eA1, sA1); rB1 = __fdividef(eB1, sB1);
            }

            float q0[8], q1[8];
#pragma unroll
            for (int k = 0; k < 8; k++) {
                q0[k] = fmaf(rB0, va1p0[k], rA0 * va0p0[k]);
                q1[k] = fmaf(rB1, va1p1[k], rA1 * va0p1[k]);
            }

            {
                const bool hi = (lane & 8) != 0;
#pragma unroll
                for (int k = 0; k < 4; k++) {
                    float s0 = hi ? q0[k] : q0[k + 4];
                    float s1 = hi ? q1[k] : q1[k + 4];
                    float r0 = __shfl_xor_sync(FULL, s0, 8);
                    float r1 = __shfl_xor_sync(FULL, s1, 8);
                    q0[k] = (hi ? q0[k + 4] : q0[k]) + r0;
                    q1[k] = (hi ? q1[k + 4] : q1[k]) + r1;
                }
            }
            {
                const bool hi = (lane & 4) != 0;
#pragma unroll
                for (int k = 0; k < 2; k++) {
                    float s0 = hi ? q0[k] : q0[k + 2];
                    float s1 = hi ? q1[k] : q1[k + 2];
                    float r0 = __shfl_xor_sync(FULL, s0, 4);
                    float r1 = __shfl_xor_sync(FULL, s1, 4);
                    q0[k] = (hi ? q0[k + 2] : q0[k]) + r0;
                    q1[k] = (hi ? q1[k + 2] : q1[k]) + r1;
                }
            }
            float s0v, s1v;
            {
                const bool hi = (lane & 2) != 0;
                float s0 = hi ? q0[0] : q0[1];
                float s1 = hi ? q1[0] : q1[1];
                float r0 = __shfl_xor_sync(FULL, s0, 2);
                float r1 = __shfl_xor_sync(FULL, s1, 2);
                s0v = (hi ? q0[1] : q0[0]) + r0;
                s1v = (hi ? q1[1] : q1[0]) + r1;
            }
            s0v += __shfl_xor_sync(FULL, s0v, 1);
            s1v += __shfl_xor_sync(FULL, s1v, 1);

            P0 = s0v + bv;
            P1 = s1v + bv;

            if (r < 2) {
                float act0[8], act1[8];
#pragma unroll
                for (int k = 0; k < 8; k++) {
                    const int src = (lane & 16) | (k << 1);
                    act0[k] = __shfl_sync(FULL, P0, src);
                    act1[k] = __shfl_sync(FULL, P1, src);
                }
                float n0 = 0.f, n1 = 0.f;
#pragma unroll
                for (int k = 0; k < 8; k++) {
                    n0 = fmaf(act0[k], act0[k], n0);
                    n1 = fmaf(act1[k], act1[k], n1);
                }
                n0 += __shfl_xor_sync(FULL, n0, 16);
                n1 += __shfl_xor_sync(FULL, n1, 16);
                const float g0 = __fdividef(sqrtf(n0), 1.f + n0);
                const float g1 = __fdividef(sqrtf(n1), 1.f + n1);

                float dA0 = 0.f, dB0 = 0.f, dA1 = 0.f, dB1 = 0.f;
#pragma unroll
                for (int k = 0; k < 8; k++) {
                    dA0 = fmaf(va0p0[k], act0[k], dA0);
                    dB0 = fmaf(va1p0[k], act0[k], dB0);
                    dA1 = fmaf(va0p1[k], act1[k], dA1);
                    dB1 = fmaf(va1p1[k], act1[k], dB1);
                }
                dA0 += __shfl_xor_sync(FULL, dA0, 16);
                dB0 += __shfl_xor_sync(FULL, dB0, 16);
                dA1 += __shfl_xor_sync(FULL, dA1, 16);
                dB1 += __shfl_xor_sync(FULL, dB1, 16);
                lA0 = fmaf(dA0, g0, lA0);  lB0 = fmaf(dB0, g0, lB0);
                lA1 = fmaf(dA1, g1, lA1);  lB1 = fmaf(dB1, g1, lB1);
            } else {
                float sq0 = P0 * P0, sq1 = P1 * P1;
#pragma unroll
                for (int off = 16; off; off >>= 1) {
                    sq0 += __shfl_xor_sync(FULL, sq0, off);
                    sq1 += __shfl_xor_sync(FULL, sq1, off);
                }
                const float n0 = 0.5f * sq0;
                const float n1 = 0.5f * sq1;
                sc0 = __fdividef(sqrtf(n0), 1.f + n0);
                sc1 = __fdividef(sqrtf(n1), 1.f + n1);
            }
        }

        const float val = (lane & 1) ? P1 * sc1 : P0 * sc0;
        out[((size_t)(b * OD + d) * OA + atom) * HWp + hw0 + 2 * q + (lane & 1)] = val;
    }
}

extern "C" void kernel_launch(void* const* d_in, const int* in_sizes, int n_in,
                              void* d_out, int out_size)
{
    const float* x    = (const float*)d_in[0];   // [32,32,16,12,12]
    const float* w    = (const float*)d_in[1];   // [32,16,160]
    const float* bias = (const float*)d_in[2];   // [10,16,1,1]
    float* out = (float*)d_out;                  // [32,10,16,12,12]

    cudaFuncSetAttribute(fused_kernel,
                         cudaFuncAttributeMaxDynamicSharedMemorySize, SMEM_BYTES);
    fused_kernel<<<Bb * NCH, 320, SMEM_BYTES>>>(x, w, bias, out);
}

// round 10
// speedup vs baseline: 1.2000x; 1.2000x over previous
#include <cuda_runtime.h>
#include <cuda_fp16.h>

// ---- problem constants ----
#define Bb   32      // batch
#define Ii   32      // input capsules
#define AIN  16      // input atoms
#define OD   10      // output classes
#define OA   16      // output atoms
#define HWp  144     // 12*12 spatial
#define Kk   160     // OD*OA
#define NPOS (Bb*HWp)   // 4608 positions

// votes scratch in fp16, layout [pos][d][i][a]  (47.2 MB)
__device__ __half g_votesh[(size_t)NPOS * Ii * Kk];

// ============================================================================
// Kernel A: votes. One block per (b, capsule-pair): 320 threads = 10 warps
// (balanced across 4 SMSPs). Threads 0-159 -> capsule i0, 160-319 -> i0+1.
// fp32 FFMA, fp16 stores.
// ============================================================================
__global__ void __launch_bounds__(320) votes_kernel(const float* __restrict__ x,
                                                    const float* __restrict__ w)
{
    const int blk  = blockIdx.x;          // b*16 + ipair
    const int b    = blk >> 4;
    const int i    = ((blk & 15) << 1) + (threadIdx.x >= 160);
    const int t    = threadIdx.x % 160;   // = d*16+a (weight column)
    const int half = threadIdx.x / 160;   // capsule slot in smem

    __shared__ __align__(16) float xs[2][AIN * HWp];   // 18 KB

    // load x[b,i,:,:] (each half loads its own capsule's 2304 floats)
    const float* xg = x + (size_t)(b * Ii + i) * (AIN * HWp);
    for (int idx = t; idx < AIN * HWp; idx += 160) xs[half][idx] = xg[idx];

    float wr[AIN];
#pragma unroll
    for (int ai = 0; ai < AIN; ai++)
        wr[ai] = w[(i * AIN + ai) * Kk + t];

    __syncthreads();

    __half* vbase = g_votesh + (size_t)(b * HWp) * (Ii * Kk)
                  + (size_t)((t >> 4) * (Ii * OA) + i * OA + (t & 15));

#pragma unroll 4
    for (int h4 = 0; h4 < HWp / 4; h4++) {
        float4 acc = make_float4(0.f, 0.f, 0.f, 0.f);
#pragma unroll
        for (int ai = 0; ai < AIN; ai++) {
            float4 xv = *(const float4*)(xs[half] + ai * HWp + h4 * 4);
            acc.x = fmaf(wr[ai], xv.x, acc.x);
            acc.y = fmaf(wr[ai], xv.y, acc.y);
            acc.z = fmaf(wr[ai], xv.z, acc.z);
            acc.w = fmaf(wr[ai], xv.w, acc.w);
        }
        __half* p = vbase + (size_t)(h4 * 4) * (Ii * Kk);
        p[0]               = __float2half_rn(acc.x);
        p[Ii * Kk]         = __float2half_rn(acc.y);
        p[2 * (Ii * Kk)]   = __float2half_rn(acc.z);
        p[3 * (Ii * Kk)]   = __float2half_rn(acc.w);
    }
}

// ============================================================================
// Kernel B: routing, 2 positions per block INTERLEAVED in registers
// (R8 phase-2 dataflow, global fp16 votes). 10 warps, warp = class d,
// lane = (i16 = capsule pair, grp = atom half).
// ============================================================================
__global__ void __launch_bounds__(320) route_kernel(const float* __restrict__ bias,
                                                    float* __restrict__ out)
{
    const int pos0 = blockIdx.x * 2;        // pos0, pos0+1 share batch b
    const int d    = threadIdx.x >> 5;
    const int lane = threadIdx.x & 31;
    const int i16  = lane & 15;
    const int grp  = lane >> 4;

    __shared__ float4 ex[2][OD][16];        // softmax exchange (eA0,eB0,eA1,eB1)

    // ---- all 4 vote loads up front (2 capsules x 2 positions) ----
    const __half* vb = g_votesh + (size_t)pos0 * (Ii * Kk)
                     + d * (Ii * OA) + (i16 * 2) * OA + grp * 8;
    uint4 raw0 = *(const uint4*)(vb);                  // pos0, cap A
    uint4 raw1 = *(const uint4*)(vb + OA);             // pos0, cap B
    uint4 raw2 = *(const uint4*)(vb + Ii * Kk);        // pos1, cap A
    uint4 raw3 = *(const uint4*)(vb + Ii * Kk + OA);   // pos1, cap B

    float va0p0[8], va1p0[8], va0p1[8], va1p1[8];
    {
        const __half2* hA0 = (const __half2*)&raw0;
        const __half2* hB0 = (const __half2*)&raw1;
        const __half2* hA1 = (const __half2*)&raw2;
        const __half2* hB1 = (const __half2*)&raw3;
#pragma unroll
        for (int k = 0; k < 4; k++) {
            float2 f;
            f = __half22float2(hA0[k]); va0p0[2*k] = f.x; va0p0[2*k+1] = f.y;
            f = __half22float2(hB0[k]); va1p0[2*k] = f.x; va1p0[2*k+1] = f.y;
            f = __half22float2(hA1[k]); va0p1[2*k] = f.x; va0p1[2*k+1] = f.y;
            f = __half22float2(hB1[k]); va1p1[2*k] = f.x; va1p1[2*k+1] = f.y;
        }
    }

    const int atom = grp * 8 + ((lane >> 1) & 7);
    const float bv = bias[d * OA + atom];
    const int b    = pos0 / HWp;
    const int hw0  = pos0 - b * HWp;
    const unsigned FULL = 0xffffffffu;

    float lA0 = 0.f, lB0 = 0.f, lA1 = 0.f, lB1 = 0.f;
    float P0 = 0.f, P1 = 0.f, sc0 = 0.f, sc1 = 0.f;

#pragma unroll
    for (int r = 0; r < 3; r++) {
        // ---- softmax over d (both positions) ----
        float rA0, rB0, rA1, rB1;
        if (r == 0) {
            rA0 = rB0 = rA1 = rB1 = 0.1f;
        } else {
            const float eA0 = __expf(lA0), eB0 = __expf(lB0);
            const float eA1 = __expf(lA1), eB1 = __expf(lB1);
            if (grp == 0) ex[r - 1][d][i16] = make_float4(eA0, eB0, eA1, eB1);
            __syncthreads();
            float sA0 = 0.f, sB0 = 0.f, sA1 = 0.f, sB1 = 0.f;
#pragma unroll
            for (int d2 = 0; d2 < OD; d2++) {
                const float4 v = ex[r - 1][d2][i16];
                sA0 += v.x; sB0 += v.y; sA1 += v.z; sB1 += v.w;
            }
            rA0 = __fdividef(eA0, sA0); rB0 = __fdividef(eB0, sB0);
            rA1 = __fdividef(eA1, sA1); rB1 = __fdividef(eB1, sB1);
        }

        // ---- weighted votes, both positions ----
        float q0[8], q1[8];
#pragma unroll
        for (int k = 0; k < 8; k++) {
            q0[k] = fmaf(rB0, va1p0[k], rA0 * va0p0[k]);
            q1[k] = fmaf(rB1, va1p1[k], rA1 * va0p1[k]);
        }

        // ---- atom-splitting reduce over 16-lane half (2 indep chains) ----
        {
            const bool hi = (lane & 8) != 0;
#pragma unroll
            for (int k = 0; k < 4; k++) {
                float s0 = hi ? q0[k] : q0[k + 4];
                float s1 = hi ? q1[k] : q1[k + 4];
                float r0 = __shfl_xor_sync(FULL, s0, 8);
                float r1 = __shfl_xor_sync(FULL, s1, 8);
                q0[k] = (hi ? q0[k + 4] : q0[k]) + r0;
                q1[k] = (hi ? q1[k + 4] : q1[k]) + r1;
            }
        }
        {
            const bool hi = (lane & 4) != 0;
#pragma unroll
            for (int k = 0; k < 2; k++) {
                float s0 = hi ? q0[k] : q0[k + 2];
                float s1 = hi ? q1[k] : q1[k + 2];
                float r0 = __shfl_xor_sync(FULL, s0, 4);
                float r1 = __shfl_xor_sync(FULL, s1, 4);
                q0[k] = (hi ? q0[k + 2] : q0[k]) + r0;
                q1[k] = (hi ? q1[k + 2] : q1[k]) + r1;
            }
        }
        float s0v, s1v;
        {
            const bool hi = (lane & 2) != 0;
            float s0 = hi ? q0[0] : q0[1];
            float s1 = hi ? q1[0] : q1[1];
            float r0 = __shfl_xor_sync(FULL, s0, 2);
            float r1 = __shfl_xor_sync(FULL, s1, 2);
            s0v = (hi ? q0[1] : q0[0]) + r0;
            s1v = (hi ? q1[1] : q1[0]) + r1;
        }
        s0v += __shfl_xor_sync(FULL, s0v, 1);
        s1v += __shfl_xor_sync(FULL, s1v, 1);

        P0 = s0v + bv;
        P1 = s1v + bv;

        if (r < 2) {
            // ---- broadcast own-group pre-squash atoms ----
            float act0[8], act1[8];
#pragma unroll
            for (int k = 0; k < 8; k++) {
                const int src = (lane & 16) | (k << 1);
                act0[k] = __shfl_sync(FULL, P0, src);
                act1[k] = __shfl_sync(FULL, P1, src);
            }
            float n0 = 0.f, n1 = 0.f;
#pragma unroll
            for (int k = 0; k < 8; k++) {
                n0 = fmaf(act0[k], act0[k], n0);
                n1 = fmaf(act1[k], act1[k], n1);
            }
            n0 += __shfl_xor_sync(FULL, n0, 16);
            n1 += __shfl_xor_sync(FULL, n1, 16);
            const float g0 = __fdividef(sqrtf(n0), 1.f + n0);
            const float g1 = __fdividef(sqrtf(n1), 1.f + n1);

            float dA0 = 0.f, dB0 = 0.f, dA1 = 0.f, dB1 = 0.f;
#pragma unroll
            for (int k = 0; k < 8; k++) {
                dA0 = fmaf(va0p0[k], act0[k], dA0);
                dB0 = fmaf(va1p0[k], act0[k], dB0);
                dA1 = fmaf(va0p1[k], act1[k], dA1);
                dB1 = fmaf(va1p1[k], act1[k], dB1);
            }
            dA0 += __shfl_xor_sync(FULL, dA0, 16);
            dB0 += __shfl_xor_sync(FULL, dB0, 16);
            dA1 += __shfl_xor_sync(FULL, dA1, 16);
            dB1 += __shfl_xor_sync(FULL, dB1, 16);
            lA0 = fmaf(dA0, g0, lA0);  lB0 = fmaf(dB0, g0, lB0);
            lA1 = fmaf(dA1, g1, lA1);  lB1 = fmaf(dB1, g1, lB1);
        } else {
            // ---- final squash norms via square-butterfly ----
            float sq0 = P0 * P0, sq1 = P1 * P1;
#pragma unroll
            for (int off = 16; off; off >>= 1) {
                sq0 += __shfl_xor_sync(FULL, sq0, off);
                sq1 += __shfl_xor_sync(FULL, sq1, off);
            }
            const float n0 = 0.5f * sq0;    // each atom counted twice
            const float n1 = 0.5f * sq1;
            sc0 = __fdividef(sqrtf(n0), 1.f + n0);
            sc1 = __fdividef(sqrtf(n1), 1.f + n1);
        }
    }

    // ---- output: even lane writes pos0, odd lane writes pos1 ----
    const float val = (lane & 1) ? P1 * sc1 : P0 * sc0;
    out[((size_t)(b * OD + d) * OA + atom) * HWp + hw0 + (lane & 1)] = val;
}

extern "C" void kernel_launch(void* const* d_in, const int* in_sizes, int n_in,
                              void* d_out, int out_size)
{
    const float* x    = (const float*)d_in[0];   // [32,32,16,12,12]
    const float* w    = (const float*)d_in[1];   // [32,16,160]
    const float* bias = (const float*)d_in[2];   // [10,16,1,1]
    float* out = (float*)d_out;                  // [32,10,16,12,12]

    votes_kernel<<<Bb * 16, 320>>>(x, w);
    route_kernel<<<NPOS / 2, 320>>>(bias, out);
}

// round 11
// speedup vs baseline: 1.3119x; 1.0932x over previous
#include <cuda_runtime.h>
#include <cuda_fp16.h>

// ---- problem constants ----
#define Bb   32      // batch
#define Ii   32      // input capsules
#define AIN  16      // input atoms
#define OD   10      // output classes
#define OA   16      // output atoms
#define HWp  144     // 12*12 spatial
#define Kk   160     // OD*OA
#define NPOS (Bb*HWp)   // 4608 positions

// votes scratch in fp16, layout [pos][d][i][a]  (47.2 MB)
__device__ __half g_votesh[(size_t)NPOS * Ii * Kk];

// ============================================================================
// Kernel A: votes[b,i,d,a,hw] = sum_ain x[b,i,ain,hw] * w[i,ain,d*16+a]
// One block per (b,i). 160 threads, t = d*16+a. 8-position inner blocking:
// 2 independent LDS.128 streams + 8 independent FFMA chains per iteration.
// ============================================================================
__global__ void __launch_bounds__(160) votes_kernel(const float* __restrict__ x,
                                                    const float* __restrict__ w)
{
    const int bi = blockIdx.x;        // b*32 + i
    const int b  = bi >> 5;
    const int i  = bi & 31;
    const int t  = threadIdx.x;       // 0..159 == d*16+a

    __shared__ __align__(16) float xs[AIN * HWp];   // 9 KB

    const float* xg = x + (size_t)bi * (AIN * HWp);
    for (int idx = t; idx < AIN * HWp; idx += 160) xs[idx] = xg[idx];

    float wr[AIN];
#pragma unroll
    for (int ai = 0; ai < AIN; ai++)
        wr[ai] = w[(i * AIN + ai) * Kk + t];

    __syncthreads();

    __half* vbase = g_votesh + (size_t)(b * HWp) * (Ii * Kk)
                  + (size_t)((t >> 4) * (Ii * OA) + i * OA + (t & 15));

#pragma unroll 2
    for (int h8 = 0; h8 < HWp / 8; h8++) {          // 18 iterations
        float4 acc0 = make_float4(0.f, 0.f, 0.f, 0.f);
        float4 acc1 = make_float4(0.f, 0.f, 0.f, 0.f);
#pragma unroll
        for (int ai = 0; ai < AIN; ai++) {
            // two independent LDS.128 broadcast streams
            const float4 xv0 = *(const float4*)(xs + ai * HWp + h8 * 8);
            const float4 xv1 = *(const float4*)(xs + ai * HWp + h8 * 8 + 4);
            acc0.x = fmaf(wr[ai], xv0.x, acc0.x);
            acc0.y = fmaf(wr[ai], xv0.y, acc0.y);
            acc0.z = fmaf(wr[ai], xv0.z, acc0.z);
            acc0.w = fmaf(wr[ai], xv0.w, acc0.w);
            acc1.x = fmaf(wr[ai], xv1.x, acc1.x);
            acc1.y = fmaf(wr[ai], xv1.y, acc1.y);
            acc1.z = fmaf(wr[ai], xv1.z, acc1.z);
            acc1.w = fmaf(wr[ai], xv1.w, acc1.w);
        }
        __half* p = vbase + (size_t)(h8 * 8) * (Ii * Kk);
        p[0]               = __float2half_rn(acc0.x);
        p[Ii * Kk]         = __float2half_rn(acc0.y);
        p[2 * (Ii * Kk)]   = __float2half_rn(acc0.z);
        p[3 * (Ii * Kk)]   = __float2half_rn(acc0.w);
        p[4 * (Ii * Kk)]   = __float2half_rn(acc1.x);
        p[5 * (Ii * Kk)]   = __float2half_rn(acc1.y);
        p[6 * (Ii * Kk)]   = __float2half_rn(acc1.z);
        p[7 * (Ii * Kk)]   = __float2half_rn(acc1.w);
    }
}

// ============================================================================
// Kernel B: routing (exact R7 structure). One block per 2 positions,
// 10 warps (warp = class d). Positions processed sequentially.
// __launch_bounds__(320, 4): target <=51 regs -> 4 blocks/SM (62.5% occ).
// ============================================================================
__global__ void __launch_bounds__(320, 4) route_kernel(const float* __restrict__ bias,
                                                       float* __restrict__ out)
{
    const int pos0 = blockIdx.x * 2;        // pos0, pos0+1 share batch b
    const int d    = threadIdx.x >> 5;      // warp id = class
    const int lane = threadIdx.x & 31;
    const int i16  = lane & 15;             // capsule pair index
    const int grp  = lane >> 4;             // atom group

    __shared__ float2 ex2[2][OD][16];       // exp(logit) pairs per softmax round

    // ---- issue all 4 vote loads (2 capsules x 2 positions) up front ----
    const __half* vb = g_votesh + (size_t)pos0 * (Ii * Kk)
                     + d * (Ii * OA) + (i16 * 2) * OA + grp * 8;
    uint4 raw[4];
    raw[0] = *(const uint4*)(vb);                   // pos0, capsule 2*i16
    raw[1] = *(const uint4*)(vb + OA);              // pos0, capsule 2*i16+1
    raw[2] = *(const uint4*)(vb + Ii * Kk);         // pos1, capsule 2*i16
    raw[3] = *(const uint4*)(vb + Ii * Kk + OA);    // pos1, capsule 2*i16+1

    const int atom = grp * 8 + ((lane >> 1) & 7);   // atom this lane owns post-reduce
    const float bv = bias[d * OA + atom];
    const int b   = pos0 / HWp;
    const int hw0 = pos0 - b * HWp;
    const unsigned FULL = 0xffffffffu;

#pragma unroll
    for (int p = 0; p < 2; p++) {
        // ---- convert this position's votes to fp32 ----
        float va0[8], va1[8];
        {
            const __half2* h0 = (const __half2*)&raw[2 * p];
            const __half2* h1 = (const __half2*)&raw[2 * p + 1];
#pragma unroll
            for (int k = 0; k < 4; k++) {
                float2 f0 = __half22float2(h0[k]);
                float2 f1 = __half22float2(h1[k]);
                va0[2 * k] = f0.x; va0[2 * k + 1] = f0.y;
                va1[2 * k] = f1.x; va1[2 * k + 1] = f1.y;
            }
        }

        float logitA = 0.f, logitB = 0.f;
        float outP = 0.f, outScale = 0.f;

#pragma unroll
        for (int r = 0; r < 3; r++) {
            // ---- softmax over d ----
            float routeA, routeB;
            if (r == 0) {
                routeA = routeB = 0.1f;
            } else {
                float e0 = __expf(logitA), e1 = __expf(logitB);
                if (grp == 0) ex2[r - 1][d][i16] = make_float2(e0, e1);
                __syncthreads();
                float sA = 0.f, sB = 0.f;
#pragma unroll
                for (int d2 = 0; d2 < OD; d2++) {
                    float2 v = ex2[r - 1][d2][i16];
                    sA += v.x; sB += v.y;
                }
                routeA = __fdividef(e0, sA);
                routeB = __fdividef(e1, sB);
            }

            // ---- q[k] = routeA*va0[k] + routeB*va1[k] (8 own-group atoms) ----
            float q[8];
#pragma unroll
            for (int k = 0; k < 8; k++)
                q[k] = fmaf(routeB, va1[k], routeA * va0[k]);

            // ---- atom-splitting reduce over 16-lane half ----
            {
                const bool hi = (lane & 8) != 0;
#pragma unroll
                for (int k = 0; k < 4; k++) {
                    float snd = hi ? q[k] : q[k + 4];
                    float rcv = __shfl_xor_sync(FULL, snd, 8);
                    q[k] = (hi ? q[k + 4] : q[k]) + rcv;
                }
            }
            {
                const bool hi = (lane & 4) != 0;
#pragma unroll
                for (int k = 0; k < 2; k++) {
                    float snd = hi ? q[k] : q[k + 2];
                    float rcv = __shfl_xor_sync(FULL, snd, 4);
                    q[k] = (hi ? q[k + 2] : q[k]) + rcv;
                }
            }
            float s;
            {
                const bool hi = (lane & 2) != 0;
                float snd = hi ? q[0] : q[1];
                float rcv = __shfl_xor_sync(FULL, snd, 2);
                s = (hi ? q[1] : q[0]) + rcv;
            }
            s += __shfl_xor_sync(FULL, s, 1);

            const float P = s + bv;         // pre-squash preact for `atom`

            if (r < 2) {
                // ---- broadcast own-group pre-squash atoms ----
                float act[8];
#pragma unroll
                for (int k = 0; k < 8; k++)
                    act[k] = __shfl_sync(FULL, P, (lane & 16) | (k << 1));

                float n2p = 0.f;
#pragma unroll
                for (int k = 0; k < 8; k++) n2p = fmaf(act[k], act[k], n2p);
                float n2 = n2p + __shfl_xor_sync(FULL, n2p, 16);
                float scale = __fdividef(sqrtf(n2), 1.f + n2);

                float dA = 0.f, dB = 0.f;
#pragma unroll
                for (int k = 0; k < 8; k++) {
                    dA = fmaf(va0[k], act[k], dA);
                    dB = fmaf(va1[k], act[k], dB);
                }
                dA += __shfl_xor_sync(FULL, dA, 16);
                dB += __shfl_xor_sync(FULL, dB, 16);
                logitA = fmaf(dA, scale, logitA);
                logitB = fmaf(dB, scale, logitB);
            } else {
                float sq = P * P;
#pragma unroll
                for (int off = 16; off; off >>= 1)
                    sq += __shfl_xor_sync(FULL, sq, off);
                float n2 = 0.5f * sq;       // each atom counted twice
                outScale = __fdividef(sqrtf(n2), 1.f + n2);
                outP = P;
            }
        }

        // ---- output: even lane of each atom pair writes ----
        if ((lane & 1) == 0) {
            out[((size_t)(b * OD + d) * OA + atom) * HWp + hw0 + p] = outP * outScale;
        }
    }
}

extern "C" void kernel_launch(void* const* d_in, const int* in_sizes, int n_in,
                              void* d_out, int out_size)
{
    const float* x    = (const float*)d_in[0];   // [32,32,16,12,12]
    const float* w    = (const float*)d_in[1];   // [32,16,160]
    const float* bias = (const float*)d_in[2];   // [10,16,1,1]
    float* out = (float*)d_out;                  // [32,10,16,12,12]

    votes_kernel<<<Bb * Ii, 160>>>(x, w);
    route_kernel<<<NPOS / 2, 320>>>(bias, out);
}